// round 2
// baseline (speedup 1.0000x reference)
#include <cuda_runtime.h>

// ---------------- scratch (device globals; no allocation allowed) ----------------
static __device__ __align__(16) float g_a1[64*32*128*128];          // enc1 out
static __device__ __align__(16) float g_a2[64*64*64*64];            // enc2 out
static __device__ __align__(16) float g_q [64*16*64*64];            // quantized (decoder input)
static __device__ __align__(16) float g_d1[64*64*128*128];          // dec1 out
static __device__ __align__(16) float g_d2[64*32*256*256];          // dec2 out
static __device__ float g_pvq [1024];                               // per-block VQ sq-sum
static __device__ float g_pmse[16384];                              // per-block recon sq-sum

// ---------------- helpers ----------------
__device__ __forceinline__ float block_sum(float v, float* sred) {
    int lane = threadIdx.x & 31, w = threadIdx.x >> 5;
    #pragma unroll
    for (int o = 16; o > 0; o >>= 1) v += __shfl_down_sync(0xffffffffu, v, o);
    if (lane == 0) sred[w] = v;
    __syncthreads();
    if (w == 0) {
        v = (lane < (int)(blockDim.x >> 5)) ? sred[lane] : 0.f;
        #pragma unroll
        for (int o = 16; o > 0; o >>= 1) v += __shfl_down_sync(0xffffffffu, v, o);
    }
    return v;  // valid in thread 0
}

#define FMA4(ACC, J, V, W4)                         \
    do {                                            \
        ACC[4*(J)+0] = fmaf(V, (W4).x, ACC[4*(J)+0]); \
        ACC[4*(J)+1] = fmaf(V, (W4).y, ACC[4*(J)+1]); \
        ACC[4*(J)+2] = fmaf(V, (W4).z, ACC[4*(J)+2]); \
        ACC[4*(J)+3] = fmaf(V, (W4).w, ACC[4*(J)+3]); \
    } while (0)

// ---------------- enc1: conv 3->32, k3 s2 p1, ReLU ----------------
// one thread per (b, oh, ow), all 32 oc in registers
__global__ void __launch_bounds__(256) k_enc1(const float* __restrict__ x,
                                              const float* __restrict__ w,
                                              const float* __restrict__ bias) {
    __shared__ __align__(16) float s_w[27 * 32];
    __shared__ float s_b[32];
    for (int i = threadIdx.x; i < 27 * 32; i += 256) {
        int oc = i & 31, t = i >> 5;               // t = ic*9 + kh*3 + kw
        s_w[i] = w[oc * 27 + t];
    }
    if (threadIdx.x < 32) s_b[threadIdx.x] = bias[threadIdx.x];
    __syncthreads();

    int tid = blockIdx.x * 256 + threadIdx.x;      // 64*128*128 threads
    int ow = tid & 127, oh = (tid >> 7) & 127, b = tid >> 14;

    float acc[32];
    #pragma unroll
    for (int oc = 0; oc < 32; oc++) acc[oc] = s_b[oc];

    #pragma unroll
    for (int ic = 0; ic < 3; ic++) {
        const float* xp = x + (size_t)(b * 3 + ic) * 65536;
        #pragma unroll
        for (int kh = 0; kh < 3; kh++) {
            int ih = oh * 2 + kh - 1;
            if ((unsigned)ih >= 256u) continue;
            #pragma unroll
            for (int kw = 0; kw < 3; kw++) {
                int iw = ow * 2 + kw - 1;
                if ((unsigned)iw >= 256u) continue;
                float v = xp[ih * 256 + iw];
                const float4* wp = (const float4*)&s_w[(ic * 9 + kh * 3 + kw) * 32];
                #pragma unroll
                for (int j = 0; j < 8; j++) { float4 w4 = wp[j]; FMA4(acc, j, v, w4); }
            }
        }
    }
    float* op = g_a1 + (size_t)b * 32 * 16384 + oh * 128 + ow;
    #pragma unroll
    for (int oc = 0; oc < 32; oc++) op[oc * 16384] = fmaxf(acc[oc], 0.f);
}

// ---------------- enc2: conv 32->64, k3 s2 p1, ReLU ----------------
__global__ void __launch_bounds__(256) k_enc2(const float* __restrict__ w,
                                              const float* __restrict__ bias) {
    extern __shared__ float sm[];
    float* s_w = sm;                 // [ic*9+t][64]  = 18432 floats
    float* s_b = sm + 288 * 64;      // 64
    for (int i = threadIdx.x; i < 288 * 64; i += 256) {
        int oc = i & 63, t = i >> 6;
        s_w[i] = w[oc * 288 + t];
    }
    if (threadIdx.x < 64) s_b[threadIdx.x] = bias[threadIdx.x];
    __syncthreads();

    int tid = blockIdx.x * 256 + threadIdx.x;      // 64*64*64 threads
    int ow = tid & 63, oh = (tid >> 6) & 63, b = tid >> 12;

    float acc[64];
    #pragma unroll
    for (int oc = 0; oc < 64; oc++) acc[oc] = s_b[oc];

    #pragma unroll 1
    for (int ic = 0; ic < 32; ic++) {
        const float* ip = g_a1 + (size_t)(b * 32 + ic) * 16384;
        #pragma unroll
        for (int kh = 0; kh < 3; kh++) {
            int ih = oh * 2 + kh - 1;
            if ((unsigned)ih >= 128u) continue;
            #pragma unroll
            for (int kw = 0; kw < 3; kw++) {
                int iw = ow * 2 + kw - 1;
                if ((unsigned)iw >= 128u) continue;
                float v = ip[ih * 128 + iw];
                const float4* wp = (const float4*)&s_w[(ic * 9 + kh * 3 + kw) * 64];
                #pragma unroll
                for (int j = 0; j < 16; j++) { float4 w4 = wp[j]; FMA4(acc, j, v, w4); }
            }
        }
    }
    float* op = g_a2 + (size_t)b * 64 * 4096 + oh * 64 + ow;
    #pragma unroll
    for (int oc = 0; oc < 64; oc++) op[oc * 4096] = fmaxf(acc[oc], 0.f);
}

// ---------------- enc3 (1x1, 64->16) + VQ + q-loss, fused ----------------
__global__ void __launch_bounds__(256) k_enc3_vq(const float* __restrict__ w3,
                                                 const float* __restrict__ b3,
                                                 const float* __restrict__ cb) {
    __shared__ __align__(16) float s_w[64 * 16];
    __shared__ float s_b[16];
    __shared__ __align__(16) float s_cb[512 * 16];
    __shared__ float s_cn[512];
    __shared__ float sred[32];

    for (int i = threadIdx.x; i < 1024; i += 256) {
        int d = i & 15, ic = i >> 4;
        s_w[i] = w3[d * 64 + ic];                  // enc_w3 is [16,64,1,1]
    }
    if (threadIdx.x < 16) s_b[threadIdx.x] = b3[threadIdx.x];
    for (int i = threadIdx.x; i < 8192; i += 256) s_cb[i] = cb[i];
    __syncthreads();
    for (int j = threadIdx.x; j < 512; j += 256) {
        float s = 0.f;
        #pragma unroll
        for (int d = 0; d < 16; d++) { float c = s_cb[j * 16 + d]; s = fmaf(c, c, s); }
        s_cn[j] = s;
    }
    __syncthreads();

    int tid = blockIdx.x * 256 + threadIdx.x;      // 64*4096 threads
    int p = tid & 4095, b = tid >> 12;

    float z[16];
    #pragma unroll
    for (int d = 0; d < 16; d++) z[d] = s_b[d];
    const float* ap = g_a2 + (size_t)b * 64 * 4096 + p;
    #pragma unroll 8
    for (int ic = 0; ic < 64; ic++) {
        float v = ap[ic * 4096];
        const float4* wp = (const float4*)&s_w[ic * 16];
        #pragma unroll
        for (int j = 0; j < 4; j++) { float4 w4 = wp[j]; FMA4(z, j, v, w4); }
    }

    // argmin_j (||c_j||^2 - 2 z.c_j)  (||z||^2 is constant per row)
    int best = 0; float bd = 3.4e38f;
    for (int j = 0; j < 512; j++) {
        const float4* cp = (const float4*)&s_cb[j * 16];
        float dot = 0.f;
        #pragma unroll
        for (int q4 = 0; q4 < 4; q4++) {
            float4 c4 = cp[q4];
            dot = fmaf(z[4*q4+0], c4.x, dot);
            dot = fmaf(z[4*q4+1], c4.y, dot);
            dot = fmaf(z[4*q4+2], c4.z, dot);
            dot = fmaf(z[4*q4+3], c4.w, dot);
        }
        float dist = s_cn[j] - 2.f * dot;
        if (dist < bd) { bd = dist; best = j; }
    }

    float sq = 0.f;
    float* qp = g_q + (size_t)b * 16 * 4096 + p;
    #pragma unroll
    for (int d = 0; d < 16; d++) {
        float qv = s_cb[best * 16 + d];
        float df = qv - z[d];
        sq = fmaf(df, df, sq);
        qp[d * 4096] = qv;                          // decoder input = quantized (STE forward)
    }
    float bs = block_sum(sq, sred);
    if (threadIdx.x == 0) g_pvq[blockIdx.x] = bs;
}

// ---------------- dec1: convT 16->64, k3 s2 p1 op1, ReLU ----------------
__global__ void __launch_bounds__(256) k_dec1(const float* __restrict__ w,
                                              const float* __restrict__ bias) {
    __shared__ __align__(16) float s_w[144 * 64];  // [(ic*9+t)][64]
    __shared__ float s_b[64];
    for (int i = threadIdx.x; i < 9216; i += 256) {
        int oc = i & 63, t9 = i >> 6;              // t9 = ic*9 + t
        int ic = t9 / 9, t = t9 - ic * 9;
        s_w[i] = w[ic * 576 + oc * 9 + t];         // dec_w1 [16,64,3,3]
    }
    if (threadIdx.x < 64) s_b[threadIdx.x] = bias[threadIdx.x];
    __syncthreads();

    int tid = blockIdx.x * 256 + threadIdx.x;      // 64*128*128 threads
    int ow = tid & 127, oh = (tid >> 7) & 127, b = tid >> 14;

    int nh = 0, khs[2], ihs[2];
    #pragma unroll
    for (int kh = 0; kh < 3; kh++) {
        int t = oh + 1 - kh;
        if (t >= 0 && !(t & 1) && (t >> 1) < 64) { khs[nh] = kh; ihs[nh] = t >> 1; nh++; }
    }
    int nw = 0, kws[2], iws[2];
    #pragma unroll
    for (int kw = 0; kw < 3; kw++) {
        int t = ow + 1 - kw;
        if (t >= 0 && !(t & 1) && (t >> 1) < 64) { kws[nw] = kw; iws[nw] = t >> 1; nw++; }
    }

    float acc[64];
    #pragma unroll
    for (int oc = 0; oc < 64; oc++) acc[oc] = s_b[oc];

    #pragma unroll 1
    for (int ic = 0; ic < 16; ic++) {
        const float* ip = g_q + (size_t)(b * 16 + ic) * 4096;
        for (int a = 0; a < nh; a++) {
            for (int c2 = 0; c2 < nw; c2++) {
                float v = ip[ihs[a] * 64 + iws[c2]];
                const float4* wp = (const float4*)&s_w[(ic * 9 + khs[a] * 3 + kws[c2]) * 64];
                #pragma unroll
                for (int j = 0; j < 16; j++) { float4 w4 = wp[j]; FMA4(acc, j, v, w4); }
            }
        }
    }
    float* op = g_d1 + (size_t)b * 64 * 16384 + oh * 128 + ow;
    #pragma unroll
    for (int oc = 0; oc < 64; oc++) op[oc * 16384] = fmaxf(acc[oc], 0.f);
}

// ---------------- dec2: convT 64->32, k3 s2 p1 op1, ReLU ----------------
__global__ void __launch_bounds__(256) k_dec2(const float* __restrict__ w,
                                              const float* __restrict__ bias) {
    extern __shared__ float sm[];
    float* s_w = sm;                 // [(ic*9+t)][32] = 18432 floats
    float* s_b = sm + 576 * 32;      // 32
    for (int i = threadIdx.x; i < 18432; i += 256) {
        int oc = i & 31, t9 = i >> 5;
        int ic = t9 / 9, t = t9 - ic * 9;
        s_w[i] = w[ic * 288 + oc * 9 + t];         // dec_w2 [64,32,3,3]
    }
    if (threadIdx.x < 32) s_b[threadIdx.x] = bias[threadIdx.x];
    __syncthreads();

    int tid = blockIdx.x * 256 + threadIdx.x;      // 64*256*256 threads
    int ow = tid & 255, oh = (tid >> 8) & 255, b = tid >> 16;

    int nh = 0, khs[2], ihs[2];
    #pragma unroll
    for (int kh = 0; kh < 3; kh++) {
        int t = oh + 1 - kh;
        if (t >= 0 && !(t & 1) && (t >> 1) < 128) { khs[nh] = kh; ihs[nh] = t >> 1; nh++; }
    }
    int nw = 0, kws[2], iws[2];
    #pragma unroll
    for (int kw = 0; kw < 3; kw++) {
        int t = ow + 1 - kw;
        if (t >= 0 && !(t & 1) && (t >> 1) < 128) { kws[nw] = kw; iws[nw] = t >> 1; nw++; }
    }

    float acc[32];
    #pragma unroll
    for (int oc = 0; oc < 32; oc++) acc[oc] = s_b[oc];

    #pragma unroll 1
    for (int ic = 0; ic < 64; ic++) {
        const float* ip = g_d1 + (size_t)(b * 64 + ic) * 16384;
        for (int a = 0; a < nh; a++) {
            for (int c2 = 0; c2 < nw; c2++) {
                float v = ip[ihs[a] * 128 + iws[c2]];
                const float4* wp = (const float4*)&s_w[(ic * 9 + khs[a] * 3 + kws[c2]) * 32];
                #pragma unroll
                for (int j = 0; j < 8; j++) { float4 w4 = wp[j]; FMA4(acc, j, v, w4); }
            }
        }
    }
    float* op = g_d2 + (size_t)b * 32 * 65536 + oh * 256 + ow;
    #pragma unroll
    for (int oc = 0; oc < 32; oc++) op[oc * 65536] = fmaxf(acc[oc], 0.f);
}

// ---------------- dec3: convT 32->3 s1 p1 == conv with flipped kernel; fused MSE ----------------
__global__ void __launch_bounds__(256) k_dec3_mse(const float* __restrict__ w,
                                                  const float* __restrict__ bias,
                                                  const float* __restrict__ x) {
    __shared__ float s_w[864];       // [(ic*9 + kh*3 + kw)][3]
    __shared__ float s_b[3];
    __shared__ float sred[32];
    for (int i = threadIdx.x; i < 864; i += 256) {
        int oc = i % 3, t9 = i / 3;
        int ic = t9 / 9, r = t9 - ic * 9, kh = r / 3, kw = r - kh * 3;
        s_w[i] = w[ic * 27 + oc * 9 + (2 - kh) * 3 + (2 - kw)];   // dec_w3 [32,3,3,3], flipped
    }
    if (threadIdx.x < 3) s_b[threadIdx.x] = bias[threadIdx.x];
    __syncthreads();

    int tid = blockIdx.x * 256 + threadIdx.x;      // 64*256*256 threads
    int ow = tid & 255, oh = (tid >> 8) & 255, b = tid >> 16;

    float r0 = s_b[0], r1 = s_b[1], r2 = s_b[2];
    #pragma unroll 1
    for (int ic = 0; ic < 32; ic++) {
        const float* ip = g_d2 + (size_t)(b * 32 + ic) * 65536;
        #pragma unroll
        for (int kh = 0; kh < 3; kh++) {
            int ih = oh + kh - 1;
            if ((unsigned)ih >= 256u) continue;
            #pragma unroll
            for (int kw = 0; kw < 3; kw++) {
                int iw = ow + kw - 1;
                if ((unsigned)iw >= 256u) continue;
                float v = ip[ih * 256 + iw];
                const float* wp = &s_w[(ic * 9 + kh * 3 + kw) * 3];
                r0 = fmaf(v, wp[0], r0);
                r1 = fmaf(v, wp[1], r1);
                r2 = fmaf(v, wp[2], r2);
            }
        }
    }
    const float* xp = x + (size_t)b * 3 * 65536 + oh * 256 + ow;
    float d0 = r0 - xp[0];
    float d1 = r1 - xp[65536];
    float d2 = r2 - xp[131072];
    float sq = fmaf(d0, d0, fmaf(d1, d1, d2 * d2));
    float bs = block_sum(sq, sred);
    if (threadIdx.x == 0) g_pmse[blockIdx.x] = bs;
}

// ---------------- deterministic final reduction ----------------
__global__ void k_final(float* __restrict__ out) {
    __shared__ double sd[256];
    double s1 = 0.0, s2 = 0.0;
    for (int i = threadIdx.x; i < 1024; i += 256)  s1 += (double)g_pvq[i];
    for (int i = threadIdx.x; i < 16384; i += 256) s2 += (double)g_pmse[i];
    sd[threadIdx.x] = s1; __syncthreads();
    for (int o = 128; o > 0; o >>= 1) {
        if ((int)threadIdx.x < o) sd[threadIdx.x] += sd[threadIdx.x + o];
        __syncthreads();
    }
    double vq = sd[0]; __syncthreads();
    sd[threadIdx.x] = s2; __syncthreads();
    for (int o = 128; o > 0; o >>= 1) {
        if ((int)threadIdx.x < o) sd[threadIdx.x] += sd[threadIdx.x + o];
        __syncthreads();
    }
    if (threadIdx.x == 0) {
        double mq = vq / 4194304.0;                 // 64*64*64*16 elements
        double mr = sd[0] / 12582912.0;             // 64*3*256*256 elements
        out[0] = (float)(1.25 * mq);                // q_latent + 0.25*e_latent (same value)
        out[1] = (float)mr;                         // recon_loss (DATA_VARIANCE=1)
        out[2] = (float)mr;                         // recon_mse
    }
}

// ---------------- launch ----------------
extern "C" void kernel_launch(void* const* d_in, const int* in_sizes, int n_in,
                              void* d_out, int out_size) {
    const float* x   = (const float*)d_in[0];
    const float* ew1 = (const float*)d_in[1];
    const float* eb1 = (const float*)d_in[2];
    const float* ew2 = (const float*)d_in[3];
    const float* eb2 = (const float*)d_in[4];
    const float* ew3 = (const float*)d_in[5];
    const float* eb3 = (const float*)d_in[6];
    const float* cb  = (const float*)d_in[7];
    const float* dw1 = (const float*)d_in[8];
    const float* db1 = (const float*)d_in[9];
    const float* dw2 = (const float*)d_in[10];
    const float* db2 = (const float*)d_in[11];
    const float* dw3 = (const float*)d_in[12];
    const float* db3 = (const float*)d_in[13];
    float* out = (float*)d_out;

    const int smem_enc2 = (288 * 64 + 64) * 4;     // 73984 B
    const int smem_dec2 = (576 * 32 + 32) * 4;     // 73856 B
    cudaFuncSetAttribute(k_enc2, cudaFuncAttributeMaxDynamicSharedMemorySize, smem_enc2);
    cudaFuncSetAttribute(k_dec2, cudaFuncAttributeMaxDynamicSharedMemorySize, smem_dec2);

    k_enc1   <<<4096, 256>>>(x, ew1, eb1);
    k_enc2   <<<1024, 256, smem_enc2>>>(ew2, eb2);
    k_enc3_vq<<<1024, 256>>>(ew3, eb3, cb);
    k_dec1   <<<4096, 256>>>(dw1, db1);
    k_dec2   <<<16384, 256, smem_dec2>>>(dw2, db2);
    k_dec3_mse<<<16384, 256>>>(dw3, db3, x);
    k_final  <<<1, 256>>>(out);
}

// round 3
// speedup vs baseline: 1.4578x; 1.4578x over previous
#include <cuda_runtime.h>

typedef unsigned long long ull;

// ---------------- scratch (device globals; no allocation allowed) ----------------
static __device__ __align__(16) float g_a1[64*32*128*128];          // enc1 out
static __device__ __align__(16) float g_a2[64*64*64*64];            // enc2 out
static __device__ __align__(16) float g_q [64*16*64*64];            // quantized (decoder input)
static __device__ __align__(16) float g_d1[64*64*128*128];          // dec1 out
static __device__ __align__(16) float g_d2[64*32*256*256];          // dec2 out
static __device__ float g_pvq [1024];                               // per-block VQ sq-sum
static __device__ float g_pmse[2048];                               // per-block recon sq-sum

// ---------------- f32x2 helpers ----------------
__device__ __forceinline__ ull pk2(float lo, float hi) {
    ull r;
    asm("mov.b64 %0, {%1, %2};" : "=l"(r)
        : "r"(__float_as_uint(lo)), "r"(__float_as_uint(hi)));
    return r;
}
__device__ __forceinline__ float2 upk2(ull p) {
    unsigned int a, b;
    asm("mov.b64 {%0, %1}, %2;" : "=r"(a), "=r"(b) : "l"(p));
    return make_float2(__uint_as_float(a), __uint_as_float(b));
}
__device__ __forceinline__ ull ffma2(ull a, ull b, ull c) {
    ull d;
    asm("fma.rn.f32x2 %0, %1, %2, %3;" : "=l"(d) : "l"(a), "l"(b), "l"(c));
    return d;
}

// ---------------- reduction helper ----------------
__device__ __forceinline__ float block_sum(float v, float* sred) {
    int lane = threadIdx.x & 31, w = threadIdx.x >> 5;
    #pragma unroll
    for (int o = 16; o > 0; o >>= 1) v += __shfl_down_sync(0xffffffffu, v, o);
    if (lane == 0) sred[w] = v;
    __syncthreads();
    if (w == 0) {
        v = (lane < (int)(blockDim.x >> 5)) ? sred[lane] : 0.f;
        #pragma unroll
        for (int o = 16; o > 0; o >>= 1) v += __shfl_down_sync(0xffffffffu, v, o);
    }
    return v;  // valid in thread 0
}

#define FMA4(ACC, J, V, W4)                         \
    do {                                            \
        ACC[4*(J)+0] = fmaf(V, (W4).x, ACC[4*(J)+0]); \
        ACC[4*(J)+1] = fmaf(V, (W4).y, ACC[4*(J)+1]); \
        ACC[4*(J)+2] = fmaf(V, (W4).z, ACC[4*(J)+2]); \
        ACC[4*(J)+3] = fmaf(V, (W4).w, ACC[4*(J)+3]); \
    } while (0)

// ---------------- enc1: conv 3->32, k3 s2 p1, ReLU (unchanged; small) ----------------
__global__ void __launch_bounds__(256) k_enc1(const float* __restrict__ x,
                                              const float* __restrict__ w,
                                              const float* __restrict__ bias) {
    __shared__ __align__(16) float s_w[27 * 32];
    __shared__ float s_b[32];
    for (int i = threadIdx.x; i < 27 * 32; i += 256) {
        int oc = i & 31, t = i >> 5;
        s_w[i] = w[oc * 27 + t];
    }
    if (threadIdx.x < 32) s_b[threadIdx.x] = bias[threadIdx.x];
    __syncthreads();

    int tid = blockIdx.x * 256 + threadIdx.x;
    int ow = tid & 127, oh = (tid >> 7) & 127, b = tid >> 14;

    float acc[32];
    #pragma unroll
    for (int oc = 0; oc < 32; oc++) acc[oc] = s_b[oc];

    #pragma unroll
    for (int ic = 0; ic < 3; ic++) {
        const float* xp = x + (size_t)(b * 3 + ic) * 65536;
        #pragma unroll
        for (int kh = 0; kh < 3; kh++) {
            int ih = oh * 2 + kh - 1;
            if ((unsigned)ih >= 256u) continue;
            #pragma unroll
            for (int kw = 0; kw < 3; kw++) {
                int iw = ow * 2 + kw - 1;
                if ((unsigned)iw >= 256u) continue;
                float v = xp[ih * 256 + iw];
                const float4* wp = (const float4*)&s_w[(ic * 9 + kh * 3 + kw) * 32];
                #pragma unroll
                for (int j = 0; j < 8; j++) { float4 w4 = wp[j]; FMA4(acc, j, v, w4); }
            }
        }
    }
    float* op = g_a1 + (size_t)b * 32 * 16384 + oh * 128 + ow;
    #pragma unroll
    for (int oc = 0; oc < 32; oc++) op[oc * 16384] = fmaxf(acc[oc], 0.f);
}

// ---------------- enc2: conv 32->64, k3 s2 p1, ReLU  (P=8 px, C=16 oc, f32x2) ----------
// block: chunk(8) x ocg(4) x row(8) = 256 threads. grid: 64b * 8 rowgroups = 512.
// smem: dup-packed weights [kh][ic][kw][oc] (w,w) = 18432 u64 + 64 bias pairs.
__global__ void __launch_bounds__(256) k_enc2(const float* __restrict__ w,
                                              const float* __restrict__ bias) {
    extern __shared__ __align__(16) ull smu[];
    ull* s_w = smu;                // 18432
    ull* s_bd = smu + 18432;       // 64
    for (int i = threadIdx.x; i < 18432; i += 256) {
        int oc = i & 63; int t = i >> 6; int kw = t % 3; t /= 3; int ic = t & 31; int kh = t >> 5;
        float wv = w[((oc * 32 + ic) * 3 + kh) * 3 + kw];
        s_w[i] = pk2(wv, wv);
    }
    if (threadIdx.x < 64) { float bv = bias[threadIdx.x]; s_bd[threadIdx.x] = pk2(bv, bv); }
    __syncthreads();

    int tx = threadIdx.x;
    int chunk = tx & 7, ocg = (tx >> 3) & 3, r = tx >> 5;
    int b = blockIdx.x >> 3, rg = blockIdx.x & 7;
    int oh = rg * 8 + r;
    int ocb = ocg * 16;
    int ow0 = chunk * 8;

    ull acc[64];
    #pragma unroll
    for (int oc = 0; oc < 16; oc++) {
        ull bp = s_bd[ocb + oc];
        acc[oc*4+0] = bp; acc[oc*4+1] = bp; acc[oc*4+2] = bp; acc[oc*4+3] = bp;
    }

    #pragma unroll 1
    for (int ic = 0; ic < 32; ic++) {
        const float* plane = g_a1 + (size_t)(b * 32 + ic) * 16384;
        #pragma unroll
        for (int kh = 0; kh < 3; kh++) {
            int ih = 2 * oh + kh - 1;
            if ((unsigned)ih >= 128u) continue;
            const float* row = plane + ih * 128 + chunk * 16;
            float vm1 = (chunk == 0) ? 0.f : row[-1];
            float4 g0 = *(const float4*)row;
            float4 g1 = *(const float4*)(row + 4);
            float4 g2 = *(const float4*)(row + 8);
            float4 g3 = *(const float4*)(row + 12);
            // pair j covers outputs (ow0+2j, ow0+2j+1); input idx rel 2*ow0
            // kw=0: (v[4j-1], v[4j+1])
            ull P00 = pk2(vm1,  g0.y), P01 = pk2(g0.w, g1.y), P02 = pk2(g1.w, g2.y), P03 = pk2(g2.w, g3.y);
            // kw=1: (v[4j],   v[4j+2])
            ull P10 = pk2(g0.x, g0.z), P11 = pk2(g1.x, g1.z), P12 = pk2(g2.x, g2.z), P13 = pk2(g3.x, g3.z);
            // kw=2: (v[4j+1], v[4j+3])
            ull P20 = pk2(g0.y, g0.w), P21 = pk2(g1.y, g1.w), P22 = pk2(g2.y, g2.w), P23 = pk2(g3.y, g3.w);
            const ull* wp0 = s_w + ((kh * 32 + ic) * 3 + 0) * 64 + ocb;
            const ull* wp1 = s_w + ((kh * 32 + ic) * 3 + 1) * 64 + ocb;
            const ull* wp2 = s_w + ((kh * 32 + ic) * 3 + 2) * 64 + ocb;
            #pragma unroll
            for (int oc = 0; oc < 16; oc++) {
                ull w0 = wp0[oc], w1 = wp1[oc], w2 = wp2[oc];
                acc[oc*4+0] = ffma2(P00, w0, ffma2(P10, w1, ffma2(P20, w2, acc[oc*4+0])));
                acc[oc*4+1] = ffma2(P01, w0, ffma2(P11, w1, ffma2(P21, w2, acc[oc*4+1])));
                acc[oc*4+2] = ffma2(P02, w0, ffma2(P12, w1, ffma2(P22, w2, acc[oc*4+2])));
                acc[oc*4+3] = ffma2(P03, w0, ffma2(P13, w1, ffma2(P23, w2, acc[oc*4+3])));
            }
        }
    }

    float* op = g_a2 + ((size_t)(b * 64 + ocb) * 64 + oh) * 64 + ow0;
    #pragma unroll
    for (int oc = 0; oc < 16; oc++) {
        float2 p0 = upk2(acc[oc*4+0]), p1 = upk2(acc[oc*4+1]);
        float2 p2 = upk2(acc[oc*4+2]), p3 = upk2(acc[oc*4+3]);
        float4 lo = make_float4(fmaxf(p0.x,0.f), fmaxf(p0.y,0.f), fmaxf(p1.x,0.f), fmaxf(p1.y,0.f));
        float4 hi = make_float4(fmaxf(p2.x,0.f), fmaxf(p2.y,0.f), fmaxf(p3.x,0.f), fmaxf(p3.y,0.f));
        *(float4*)(op + (size_t)oc * 4096) = lo;
        *(float4*)(op + (size_t)oc * 4096 + 4) = hi;
    }
}

// ---------------- enc3 (1x1, 64->16) + VQ + q-loss (unchanged) ----------------
__global__ void __launch_bounds__(256) k_enc3_vq(const float* __restrict__ w3,
                                                 const float* __restrict__ b3,
                                                 const float* __restrict__ cb) {
    __shared__ __align__(16) float s_w[64 * 16];
    __shared__ float s_b[16];
    __shared__ __align__(16) float s_cb[512 * 16];
    __shared__ float s_cn[512];
    __shared__ float sred[32];

    for (int i = threadIdx.x; i < 1024; i += 256) {
        int d = i & 15, ic = i >> 4;
        s_w[i] = w3[d * 64 + ic];
    }
    if (threadIdx.x < 16) s_b[threadIdx.x] = b3[threadIdx.x];
    for (int i = threadIdx.x; i < 8192; i += 256) s_cb[i] = cb[i];
    __syncthreads();
    for (int j = threadIdx.x; j < 512; j += 256) {
        float s = 0.f;
        #pragma unroll
        for (int d = 0; d < 16; d++) { float c = s_cb[j * 16 + d]; s = fmaf(c, c, s); }
        s_cn[j] = s;
    }
    __syncthreads();

    int tid = blockIdx.x * 256 + threadIdx.x;
    int p = tid & 4095, b = tid >> 12;

    float z[16];
    #pragma unroll
    for (int d = 0; d < 16; d++) z[d] = s_b[d];
    const float* ap = g_a2 + (size_t)b * 64 * 4096 + p;
    #pragma unroll 8
    for (int ic = 0; ic < 64; ic++) {
        float v = ap[ic * 4096];
        const float4* wp = (const float4*)&s_w[ic * 16];
        #pragma unroll
        for (int j = 0; j < 4; j++) { float4 w4 = wp[j]; FMA4(z, j, v, w4); }
    }

    int best = 0; float bd = 3.4e38f;
    for (int j = 0; j < 512; j++) {
        const float4* cp = (const float4*)&s_cb[j * 16];
        float dot = 0.f;
        #pragma unroll
        for (int q4 = 0; q4 < 4; q4++) {
            float4 c4 = cp[q4];
            dot = fmaf(z[4*q4+0], c4.x, dot);
            dot = fmaf(z[4*q4+1], c4.y, dot);
            dot = fmaf(z[4*q4+2], c4.z, dot);
            dot = fmaf(z[4*q4+3], c4.w, dot);
        }
        float dist = s_cn[j] - 2.f * dot;
        if (dist < bd) { bd = dist; best = j; }
    }

    float sq = 0.f;
    float* qp = g_q + (size_t)b * 16 * 4096 + p;
    #pragma unroll
    for (int d = 0; d < 16; d++) {
        float qv = s_cb[best * 16 + d];
        float df = qv - z[d];
        sq = fmaf(df, df, sq);
        qp[d * 4096] = qv;
    }
    float bs = block_sum(sq, sred);
    if (threadIdx.x == 0) g_pvq[blockIdx.x] = bs;
}

// ---------------- dec1: convT 16->64 k3 s2 p1 op1, ReLU (parity-rows, P=8, C=16, f32x2)
// block: chunk(16) x ocg(4) x r(4) = 256. grid: 64b * 2ph * 16rg = 2048.
// smem weights [kh][ic][oc] -> {(w1,w2),(0,w0)} : 6144 u64 + 64 bias pairs (dynamic)
__global__ void __launch_bounds__(256) k_dec1(const float* __restrict__ w,
                                              const float* __restrict__ bias) {
    extern __shared__ __align__(16) ull smu[];
    ull* s_w = smu;               // 6144
    ull* s_bd = smu + 6144;       // 64
    for (int i = threadIdx.x; i < 6144; i += 256) {
        int h = i & 1; int t = i >> 1; int oc = t & 63; int t2 = t >> 6; int ic = t2 & 15; int kh = t2 >> 4;
        const float* wb = w + ((ic * 64 + oc) * 3 + kh) * 3;   // dec_w1 [16][64][3][3]
        s_w[i] = h ? pk2(0.f, wb[0]) : pk2(wb[1], wb[2]);
    }
    if (threadIdx.x < 64) { float bv = bias[threadIdx.x]; s_bd[threadIdx.x] = pk2(bv, bv); }
    __syncthreads();

    int tx = threadIdx.x;
    int chunk = tx & 15, ocg = (tx >> 4) & 3, r = tx >> 6;
    int bi = blockIdx.x;
    int b = bi >> 5; int rem = bi & 31; int ph = rem >> 4; int rg = rem & 15;
    int R = rg * 4 + r;
    int oh = 2 * R + ph;
    int ocb = ocg * 16;
    int ow0 = chunk * 8;

    int nt, khs[2], ihs[2];
    if (ph == 0) { khs[0] = 1; ihs[0] = R; nt = 1; }
    else { khs[0] = 2; ihs[0] = R; nt = 1; if (R + 1 < 64) { khs[1] = 0; ihs[1] = R + 1; nt = 2; } }

    ull acc[64];
    #pragma unroll
    for (int oc = 0; oc < 16; oc++) {
        ull bp = s_bd[ocb + oc];
        acc[oc*4+0] = bp; acc[oc*4+1] = bp; acc[oc*4+2] = bp; acc[oc*4+3] = bp;
    }

    #pragma unroll 1
    for (int ic = 0; ic < 16; ic++) {
        const float* plane = g_q + (size_t)(b * 16 + ic) * 4096;
        for (int a = 0; a < nt; a++) {
            const float* row = plane + ihs[a] * 64 + chunk * 4;
            float4 f = *(const float4*)row;
            float v4 = (chunk < 15) ? row[4] : 0.f;
            ull d0 = pk2(f.x, f.x), d1 = pk2(f.y, f.y), d2 = pk2(f.z, f.z), d3 = pk2(f.w, f.w);
            ull o0 = pk2(f.x, f.y), o1 = pk2(f.y, f.z), o2 = pk2(f.z, f.w), o3 = pk2(f.w, v4);
            const ull* wp = s_w + ((khs[a] * 16 + ic) * 64 + ocb) * 2;
            #pragma unroll
            for (int oc = 0; oc < 16; oc++) {
                ulonglong2 wq = *(const ulonglong2*)(wp + oc * 2);  // (w1,w2), (0,w0)
                acc[oc*4+0] = ffma2(d0, wq.x, ffma2(o0, wq.y, acc[oc*4+0]));
                acc[oc*4+1] = ffma2(d1, wq.x, ffma2(o1, wq.y, acc[oc*4+1]));
                acc[oc*4+2] = ffma2(d2, wq.x, ffma2(o2, wq.y, acc[oc*4+2]));
                acc[oc*4+3] = ffma2(d3, wq.x, ffma2(o3, wq.y, acc[oc*4+3]));
            }
        }
    }

    float* op = g_d1 + ((size_t)(b * 64 + ocb) * 128 + oh) * 128 + ow0;
    #pragma unroll
    for (int oc = 0; oc < 16; oc++) {
        float2 p0 = upk2(acc[oc*4+0]), p1 = upk2(acc[oc*4+1]);
        float2 p2 = upk2(acc[oc*4+2]), p3 = upk2(acc[oc*4+3]);
        float4 lo = make_float4(fmaxf(p0.x,0.f), fmaxf(p0.y,0.f), fmaxf(p1.x,0.f), fmaxf(p1.y,0.f));
        float4 hi = make_float4(fmaxf(p2.x,0.f), fmaxf(p2.y,0.f), fmaxf(p3.x,0.f), fmaxf(p3.y,0.f));
        *(float4*)(op + (size_t)oc * 16384) = lo;
        *(float4*)(op + (size_t)oc * 16384 + 4) = hi;
    }
}

// ---------------- dec2: convT 64->32 k3 s2 p1 op1, ReLU (parity-rows, P=8, C=16, f32x2)
// block: chunk(32) x ocg(2) x r(4) = 256. grid: 64b * 2ph * 32rg = 4096.
// smem weights [kh][ic][oc] pairs: 12288 u64 + 32 bias pairs (dynamic, 98.5KB)
__global__ void __launch_bounds__(256) k_dec2(const float* __restrict__ w,
                                              const float* __restrict__ bias) {
    extern __shared__ __align__(16) ull smu[];
    ull* s_w = smu;                // 12288
    ull* s_bd = smu + 12288;       // 32
    for (int i = threadIdx.x; i < 12288; i += 256) {
        int h = i & 1; int t = i >> 1; int oc = t & 31; int t2 = t >> 5; int ic = t2 & 63; int kh = t2 >> 6;
        const float* wb = w + ((ic * 32 + oc) * 3 + kh) * 3;   // dec_w2 [64][32][3][3]
        s_w[i] = h ? pk2(0.f, wb[0]) : pk2(wb[1], wb[2]);
    }
    if (threadIdx.x < 32) { float bv = bias[threadIdx.x]; s_bd[threadIdx.x] = pk2(bv, bv); }
    __syncthreads();

    int tx = threadIdx.x;
    int chunk = tx & 31, ocg = (tx >> 5) & 1, r = tx >> 6;
    int bi = blockIdx.x;
    int b = bi >> 6; int rem = bi & 63; int ph = rem >> 5; int rg = rem & 31;
    int R = rg * 4 + r;
    int oh = 2 * R + ph;
    int ocb = ocg * 16;
    int ow0 = chunk * 8;

    int nt, khs[2], ihs[2];
    if (ph == 0) { khs[0] = 1; ihs[0] = R; nt = 1; }
    else { khs[0] = 2; ihs[0] = R; nt = 1; if (R + 1 < 128) { khs[1] = 0; ihs[1] = R + 1; nt = 2; } }

    ull acc[64];
    #pragma unroll
    for (int oc = 0; oc < 16; oc++) {
        ull bp = s_bd[ocb + oc];
        acc[oc*4+0] = bp; acc[oc*4+1] = bp; acc[oc*4+2] = bp; acc[oc*4+3] = bp;
    }

    #pragma unroll 1
    for (int ic = 0; ic < 64; ic++) {
        const float* plane = g_d1 + (size_t)(b * 64 + ic) * 16384;
        for (int a = 0; a < nt; a++) {
            const float* row = plane + ihs[a] * 128 + chunk * 4;
            float4 f = *(const float4*)row;
            float v4 = (chunk < 31) ? row[4] : 0.f;
            ull d0 = pk2(f.x, f.x), d1 = pk2(f.y, f.y), d2 = pk2(f.z, f.z), d3 = pk2(f.w, f.w);
            ull o0 = pk2(f.x, f.y), o1 = pk2(f.y, f.z), o2 = pk2(f.z, f.w), o3 = pk2(f.w, v4);
            const ull* wp = s_w + ((khs[a] * 64 + ic) * 32 + ocb) * 2;
            #pragma unroll
            for (int oc = 0; oc < 16; oc++) {
                ulonglong2 wq = *(const ulonglong2*)(wp + oc * 2);  // (w1,w2), (0,w0)
                acc[oc*4+0] = ffma2(d0, wq.x, ffma2(o0, wq.y, acc[oc*4+0]));
                acc[oc*4+1] = ffma2(d1, wq.x, ffma2(o1, wq.y, acc[oc*4+1]));
                acc[oc*4+2] = ffma2(d2, wq.x, ffma2(o2, wq.y, acc[oc*4+2]));
                acc[oc*4+3] = ffma2(d3, wq.x, ffma2(o3, wq.y, acc[oc*4+3]));
            }
        }
    }

    float* op = g_d2 + ((size_t)(b * 32 + ocb) * 256 + oh) * 256 + ow0;
    #pragma unroll
    for (int oc = 0; oc < 16; oc++) {
        float2 p0 = upk2(acc[oc*4+0]), p1 = upk2(acc[oc*4+1]);
        float2 p2 = upk2(acc[oc*4+2]), p3 = upk2(acc[oc*4+3]);
        float4 lo = make_float4(fmaxf(p0.x,0.f), fmaxf(p0.y,0.f), fmaxf(p1.x,0.f), fmaxf(p1.y,0.f));
        float4 hi = make_float4(fmaxf(p2.x,0.f), fmaxf(p2.y,0.f), fmaxf(p3.x,0.f), fmaxf(p3.y,0.f));
        *(float4*)(op + (size_t)oc * 65536) = lo;
        *(float4*)(op + (size_t)oc * 65536 + 4) = hi;
    }
}

// ---------------- dec3: convT 32->3 s1 p1 (== conv w/ flipped kernel) + fused MSE
// P=8 pixels/thread, pixel-pair f32x2. block: chunk(32) x r(8) = 256. grid: 64b*32rg = 2048.
__global__ void __launch_bounds__(256) k_dec3_mse(const float* __restrict__ w,
                                                  const float* __restrict__ bias,
                                                  const float* __restrict__ x) {
    __shared__ __align__(16) ull s_wd[864];   // [ic][kh][kw][oc] dup pairs
    __shared__ ull s_bd[3];
    __shared__ float sred[32];
    for (int i = threadIdx.x; i < 864; i += 256) {
        int oc = i % 3; int t = i / 3; int kw = t % 3; t /= 3; int kh = t % 3; int ic = t / 3;
        float wv = w[ic * 27 + oc * 9 + (2 - kh) * 3 + (2 - kw)];   // dec_w3 [32][3][3][3] flipped
        s_wd[i] = pk2(wv, wv);
    }
    if (threadIdx.x < 3) { float bv = bias[threadIdx.x]; s_bd[threadIdx.x] = pk2(bv, bv); }
    __syncthreads();

    int tx = threadIdx.x;
    int chunk = tx & 31, r = tx >> 5;
    int b = blockIdx.x >> 5, rg = blockIdx.x & 31;
    int oh = rg * 8 + r;
    int ow0 = chunk * 8;

    ull acc[12];
    #pragma unroll
    for (int oc = 0; oc < 3; oc++) {
        ull bp = s_bd[oc];
        acc[oc*4+0] = bp; acc[oc*4+1] = bp; acc[oc*4+2] = bp; acc[oc*4+3] = bp;
    }

    #pragma unroll 1
    for (int ic = 0; ic < 32; ic++) {
        const float* plane = g_d2 + (size_t)(b * 32 + ic) * 65536;
        #pragma unroll
        for (int kh = 0; kh < 3; kh++) {
            int ih = oh + kh - 1;
            if ((unsigned)ih >= 256u) continue;
            const float* row = plane + ih * 256 + ow0;
            float4 f0 = *(const float4*)row;
            float4 f1 = *(const float4*)(row + 4);
            float vm1 = (chunk == 0) ? 0.f : row[-1];
            float v8  = (chunk == 31) ? 0.f : row[8];
            ull A0 = pk2(f0.x, f0.y), A1 = pk2(f0.z, f0.w), A2 = pk2(f1.x, f1.y), A3 = pk2(f1.z, f1.w);
            ull O0 = pk2(vm1, f0.x), O1 = pk2(f0.y, f0.z), O2 = pk2(f0.w, f1.x),
                O3 = pk2(f1.y, f1.z), O4 = pk2(f1.w, v8);
            const ull* wp = s_wd + (ic * 3 + kh) * 9;   // [kw][oc]
            #pragma unroll
            for (int oc = 0; oc < 3; oc++) {
                ull w0 = wp[oc], w1 = wp[3 + oc], w2 = wp[6 + oc];
                acc[oc*4+0] = ffma2(O0, w0, ffma2(A0, w1, ffma2(O1, w2, acc[oc*4+0])));
                acc[oc*4+1] = ffma2(O1, w0, ffma2(A1, w1, ffma2(O2, w2, acc[oc*4+1])));
                acc[oc*4+2] = ffma2(O2, w0, ffma2(A2, w1, ffma2(O3, w2, acc[oc*4+2])));
                acc[oc*4+3] = ffma2(O3, w0, ffma2(A3, w1, ffma2(O4, w2, acc[oc*4+3])));
            }
        }
    }

    const float* xp = x + (size_t)b * 3 * 65536 + oh * 256 + ow0;
    float sq = 0.f;
    #pragma unroll
    for (int oc = 0; oc < 3; oc++) {
        float4 x0 = *(const float4*)(xp + (size_t)oc * 65536);
        float4 x1 = *(const float4*)(xp + (size_t)oc * 65536 + 4);
        float2 p0 = upk2(acc[oc*4+0]), p1 = upk2(acc[oc*4+1]);
        float2 p2 = upk2(acc[oc*4+2]), p3 = upk2(acc[oc*4+3]);
        float e;
        e = p0.x - x0.x; sq = fmaf(e, e, sq);
        e = p0.y - x0.y; sq = fmaf(e, e, sq);
        e = p1.x - x0.z; sq = fmaf(e, e, sq);
        e = p1.y - x0.w; sq = fmaf(e, e, sq);
        e = p2.x - x1.x; sq = fmaf(e, e, sq);
        e = p2.y - x1.y; sq = fmaf(e, e, sq);
        e = p3.x - x1.z; sq = fmaf(e, e, sq);
        e = p3.y - x1.w; sq = fmaf(e, e, sq);
    }
    float bs = block_sum(sq, sred);
    if (threadIdx.x == 0) g_pmse[blockIdx.x] = bs;
}

// ---------------- deterministic final reduction ----------------
__global__ void k_final(float* __restrict__ out) {
    __shared__ double sd[256];
    double s1 = 0.0, s2 = 0.0;
    for (int i = threadIdx.x; i < 1024; i += 256) s1 += (double)g_pvq[i];
    for (int i = threadIdx.x; i < 2048; i += 256) s2 += (double)g_pmse[i];
    sd[threadIdx.x] = s1; __syncthreads();
    for (int o = 128; o > 0; o >>= 1) {
        if ((int)threadIdx.x < o) sd[threadIdx.x] += sd[threadIdx.x + o];
        __syncthreads();
    }
    double vq = sd[0]; __syncthreads();
    sd[threadIdx.x] = s2; __syncthreads();
    for (int o = 128; o > 0; o >>= 1) {
        if ((int)threadIdx.x < o) sd[threadIdx.x] += sd[threadIdx.x + o];
        __syncthreads();
    }
    if (threadIdx.x == 0) {
        double mq = vq / 4194304.0;                 // 64*64*64*16
        double mr = sd[0] / 12582912.0;             // 64*3*256*256
        out[0] = (float)(1.25 * mq);
        out[1] = (float)mr;
        out[2] = (float)mr;
    }
}

// ---------------- launch ----------------
extern "C" void kernel_launch(void* const* d_in, const int* in_sizes, int n_in,
                              void* d_out, int out_size) {
    const float* x   = (const float*)d_in[0];
    const float* ew1 = (const float*)d_in[1];
    const float* eb1 = (const float*)d_in[2];
    const float* ew2 = (const float*)d_in[3];
    const float* eb2 = (const float*)d_in[4];
    const float* ew3 = (const float*)d_in[5];
    const float* eb3 = (const float*)d_in[6];
    const float* cb  = (const float*)d_in[7];
    const float* dw1 = (const float*)d_in[8];
    const float* db1 = (const float*)d_in[9];
    const float* dw2 = (const float*)d_in[10];
    const float* db2 = (const float*)d_in[11];
    const float* dw3 = (const float*)d_in[12];
    const float* db3 = (const float*)d_in[13];
    float* out = (float*)d_out;

    const int smem_enc2 = (18432 + 64) * 8;   // 147968 B
    const int smem_dec1 = (6144 + 64) * 8;    // 49664 B
    const int smem_dec2 = (12288 + 32) * 8;   // 98560 B
    cudaFuncSetAttribute(k_enc2, cudaFuncAttributeMaxDynamicSharedMemorySize, smem_enc2);
    cudaFuncSetAttribute(k_dec1, cudaFuncAttributeMaxDynamicSharedMemorySize, smem_dec1);
    cudaFuncSetAttribute(k_dec2, cudaFuncAttributeMaxDynamicSharedMemorySize, smem_dec2);

    k_enc1    <<<4096, 256>>>(x, ew1, eb1);
    k_enc2    <<<512, 256, smem_enc2>>>(ew2, eb2);
    k_enc3_vq <<<1024, 256>>>(ew3, eb3, cb);
    k_dec1    <<<2048, 256, smem_dec1>>>(dw1, db1);
    k_dec2    <<<4096, 256, smem_dec2>>>(dw2, db2);
    k_dec3_mse<<<2048, 256>>>(dw3, db3, x);
    k_final   <<<1, 256>>>(out);
}